// round 4
// baseline (speedup 1.0000x reference)
#include <cuda_runtime.h>
#include <cuda_bf16.h>

// x[B=16, H=256, W=256, C=3, L=8] fp32 -> out[16,3,8,8]
// CHN = C*L = 24 floats = 6 float4 per (b,h,w).
#define HW    256
#define CHN   24
#define CHUNK 32          // output cols per CTA
#define RT    64          // output rows per CTA
#define BLK   192
#define HALO  7
#define NCMAX (CHUNK + HALO)       // 39 cols incl. halo
#define NFMAX (NCMAX * 6)          // 234 float4 items per plane row
#define P2W   204                  // p2 plane width (34 cols * 6)
#define ST2   210                  // p2 row stride (== 2 mod 8 -> conflict-free)
#define ST4   234                  // p4 row stride (== 2 mod 8)
#define SMEM_F4  (8 * ST2 + 8 * ST4)   // 3552 float4
#define SMEMBYTES (SMEM_F4 * 16)       // 56832 B -> 3 CTAs/SM

__device__ __forceinline__ float4 fmax4(float4 a, float4 b) {
    return make_float4(fmaxf(a.x, b.x), fmaxf(a.y, b.y),
                       fmaxf(a.z, b.z), fmaxf(a.w, b.w));
}
__device__ __forceinline__ void fadd4(float4& a, float4 b) {
    a.x += b.x; a.y += b.y; a.z += b.z; a.w += b.w;
}

// CTA = (batch, 64-row strip, 32-col chunk + 7 halo cols). Streams rows once.
// Load phase (per 4-row batch): p2[r]=max(x[r],x[r+1]) and p4[r]=max over 4
// rows land in 8-slot smem rings; p2 writes are delayed 2 rows (store p2m2)
// so both rings fit 8 slots. Phase B: thread=(ri,ch4,g) computes horizontal
// window maxes for 4 cols of one output row with m2/m4 doubling; per-scale
// sums accumulate in registers; block reduce + atomics at the end.
__global__ __launch_bounds__(BLK, 3)
void sgb_main(const float* __restrict__ x, float* __restrict__ out) {
    extern __shared__ float4 sm[];
    float4* P2 = sm;                  // 8 x ST2
    float4* P4 = sm + 8 * ST2;        // 8 x ST4

    const int t  = threadIdx.x;
    const int b  = blockIdx.z;
    const int r0 = blockIdx.y * RT;
    const int c0 = blockIdx.x * CHUNK;
    const int ncols = min(NCMAX, HW - c0);
    const int NF = ncols * 6;

    // load-phase state: item0 = t (own cols), item1 = t+BLK (halo cols)
    const bool has2 = (t + BLK < NF);
    float4 xp0 = {0,0,0,0}, m1_0 = {0,0,0,0}, m2_0 = {0,0,0,0};
    float4 xp1 = {0,0,0,0}, m1_1 = {0,0,0,0}, m2_1 = {0,0,0,0};

    // phase-B mapping: t = ((g*6 + ch4)*4 + ri), g in 0..7, T=4 cols
    const int ri  = t & 3;
    const int gch = t >> 2;
    const int ch4 = gch % 6;
    const int g   = gch / 6;
    const int baseitem = g * 24 + ch4;
    const int collim = HW - (c0 + g * 4);   // col j valid for scale s iff j+s<=collim

    float4 acc[8];
#pragma unroll
    for (int s = 0; s < 8; ++s) acc[s] = make_float4(0.f, 0.f, 0.f, 0.f);

    const float4* X = (const float4*)x;
    int loaded = r0;

    for (int i = r0; i < r0 + RT; i += 4) {
        const int rowend = min(i + 10, HW - 1);
        for (; loaded <= rowend; ++loaded) {
            const int rr = loaded;
            const float4* grow = X + ((size_t)(b * HW + rr) * HW + c0) * 6;
            {   // item 0: f = t (always an own col, t < 192)
                float4 xv = grow[t];
                if (rr < r0 + RT) fadd4(acc[0], xv);       // scale 1
                if (rr > r0) {
                    float4 p2v = fmax4(xv, xp0);           // p2[rr-1]
                    if (rr >= r0 + 3) {
                        const int ws = (rr - 3) & 7;
                        P2[ws * ST2 + t] = m2_0;           // p2[rr-3]
                        P4[ws * ST4 + t] = fmax4(m2_0, p2v); // p4[rr-3]
                    }
                    if (rr == HW - 1) {                    // bottom-edge p2 flush
                        P2[((rr - 2) & 7) * ST2 + t] = m1_0;
                        P2[((rr - 1) & 7) * ST2 + t] = p2v;
                    }
                    m2_0 = m1_0; m1_0 = p2v;
                }
                xp0 = xv;
            }
            if (has2) {  // item 1: halo col, no scale-1 add
                const int f = t + BLK;
                float4 xv = grow[f];
                if (rr > r0) {
                    float4 p2v = fmax4(xv, xp1);
                    if (rr >= r0 + 3) {
                        const int ws = (rr - 3) & 7;
                        if (f < P2W) P2[ws * ST2 + f] = m2_1;
                        P4[ws * ST4 + f] = fmax4(m2_1, p2v);
                    }
                    if (rr == HW - 1 && f < P2W) {
                        P2[((rr - 2) & 7) * ST2 + f] = m1_1;
                        P2[((rr - 1) & 7) * ST2 + f] = p2v;
                    }
                    m2_1 = m1_1; m1_1 = p2v;
                }
                xp1 = xv;
            }
        }
        __syncthreads();

        // ---- phase B: output row o = i + ri ----
        const int o = i + ri;
        const int rlim = HW - o;
        const float4* p2o  = P2 + ((o    ) & 7) * ST2 + baseitem;
        const float4* p2o1 = P2 + ((o + 1) & 7) * ST2 + baseitem;
        const float4* p4o  = P4 + ((o    ) & 7) * ST4 + baseitem;
        const float4* p4o1 = P4 + ((o + 1) & 7) * ST4 + baseitem;
        const float4* p4o2 = P4 + ((o + 2) & 7) * ST4 + baseitem;
        const float4* p4o3 = P4 + ((o + 3) & 7) * ST4 + baseitem;
        const float4* p4o4 = P4 + ((o + 4) & 7) * ST4 + baseitem;

        // scales 2,3 from p2
        {
            float4 a[6];
#pragma unroll
            for (int k = 0; k < 6; ++k) a[k] = p2o[6 * k];
            if (rlim >= 2) {
                float4 s = make_float4(0.f, 0.f, 0.f, 0.f);
#pragma unroll
                for (int j = 0; j < 4; ++j)
                    if (j + 2 <= collim) fadd4(s, fmax4(a[j], a[j + 1]));
                fadd4(acc[1], s);
            }
            if (rlim >= 3) {
                float4 bb[6];
#pragma unroll
                for (int k = 0; k < 6; ++k) bb[k] = fmax4(a[k], p2o1[6 * k]);
                float4 s = make_float4(0.f, 0.f, 0.f, 0.f);
#pragma unroll
                for (int j = 0; j < 4; ++j)
                    if (j + 3 <= collim)
                        fadd4(s, fmax4(fmax4(bb[j], bb[j + 1]), bb[j + 2]));
                fadd4(acc[2], s);
            }
        }
        // scales 4..8 from p4
        {
            float4 a4[11];
#pragma unroll
            for (int k = 0; k < 11; ++k) a4[k] = p4o[6 * k];
            if (rlim >= 4) {
                float4 m2[6];
#pragma unroll
                for (int k = 0; k < 6; ++k) m2[k] = fmax4(a4[k], a4[k + 1]);
                float4 s = make_float4(0.f, 0.f, 0.f, 0.f);
#pragma unroll
                for (int j = 0; j < 4; ++j)
                    if (j + 4 <= collim) fadd4(s, fmax4(m2[j], m2[j + 2]));
                fadd4(acc[3], s);
            }
            if (rlim >= 5) {
                float4 bb[8];
#pragma unroll
                for (int k = 0; k < 8; ++k) bb[k] = fmax4(a4[k], p4o1[6 * k]);
                float4 m2[6];
#pragma unroll
                for (int k = 0; k < 6; ++k) m2[k] = fmax4(bb[k], bb[k + 1]);
                float4 s = make_float4(0.f, 0.f, 0.f, 0.f);
#pragma unroll
                for (int j = 0; j < 4; ++j)
                    if (j + 5 <= collim)
                        fadd4(s, fmax4(fmax4(m2[j], m2[j + 2]), bb[j + 4]));
                fadd4(acc[4], s);
            }
            if (rlim >= 6) {
                float4 bb[9];
#pragma unroll
                for (int k = 0; k < 9; ++k) bb[k] = fmax4(a4[k], p4o2[6 * k]);
                float4 m2[8];
#pragma unroll
                for (int k = 0; k < 8; ++k) m2[k] = fmax4(bb[k], bb[k + 1]);
                float4 s = make_float4(0.f, 0.f, 0.f, 0.f);
#pragma unroll
                for (int j = 0; j < 4; ++j)
                    if (j + 6 <= collim)
                        fadd4(s, fmax4(fmax4(m2[j], m2[j + 2]), m2[j + 4]));
                fadd4(acc[5], s);
            }
            if (rlim >= 7) {
                float4 bb[10];
#pragma unroll
                for (int k = 0; k < 10; ++k) bb[k] = fmax4(a4[k], p4o3[6 * k]);
                float4 m2[9];
#pragma unroll
                for (int k = 0; k < 9; ++k) m2[k] = fmax4(bb[k], bb[k + 1]);
                float4 m4[7];
#pragma unroll
                for (int j = 0; j < 7; ++j) m4[j] = fmax4(m2[j], m2[j + 2]);
                float4 s = make_float4(0.f, 0.f, 0.f, 0.f);
#pragma unroll
                for (int j = 0; j < 4; ++j)
                    if (j + 7 <= collim) fadd4(s, fmax4(m4[j], m4[j + 3]));
                fadd4(acc[6], s);
            }
            if (rlim >= 8) {
                float4 bb[11];
#pragma unroll
                for (int k = 0; k < 11; ++k) bb[k] = fmax4(a4[k], p4o4[6 * k]);
                float4 m2[10];
#pragma unroll
                for (int k = 0; k < 10; ++k) m2[k] = fmax4(bb[k], bb[k + 1]);
                float4 m4[8];
#pragma unroll
                for (int j = 0; j < 8; ++j) m4[j] = fmax4(m2[j], m2[j + 2]);
                float4 s = make_float4(0.f, 0.f, 0.f, 0.f);
#pragma unroll
                for (int j = 0; j < 4; ++j)
                    if (j + 8 <= collim) fadd4(s, fmax4(m4[j], m4[j + 4]));
                fadd4(acc[7], s);
            }
        }
        __syncthreads();   // tight rings: next load clobbers slots read above
    }

    // ---- block reduction: 32 owners per (ch4, scale); stride 33 kills conflicts
    __syncthreads();
    float4* red = sm;                 // 48*33 = 1584 float4, reuses rings
    red[((t % 6) * 8 + 0) * 33 + (t / 6)] = acc[0];     // scale 1 (load mapping)
#pragma unroll
    for (int si = 1; si < 8; ++si)
        red[(ch4 * 8 + si) * 33 + (g * 4 + ri)] = acc[si];
    __syncthreads();
    if (t < 48) {
        const int c4 = t >> 3, si = t & 7;
        float4 s = make_float4(0.f, 0.f, 0.f, 0.f);
        const float4* row = red + (c4 * 8 + si) * 33;
#pragma unroll 8
        for (int w = 0; w < 32; ++w) fadd4(s, row[w]);
        float* op = out + (size_t)b * (CHN * 8) + si;
        atomicAdd(op + (c4 * 4 + 0) * 8, s.x);
        atomicAdd(op + (c4 * 4 + 1) * 8, s.y);
        atomicAdd(op + (c4 * 4 + 2) * 8, s.z);
        atomicAdd(op + (c4 * 4 + 3) * 8, s.w);
    }
}

__global__ void sgb_zero(float* __restrict__ out) {
    int i = blockIdx.x * blockDim.x + threadIdx.x;
    if (i < 16 * CHN * 8) out[i] = 0.f;
}

__global__ void sgb_finalize(float* __restrict__ out) {
    int i = blockIdx.x * blockDim.x + threadIdx.x;
    if (i < 16 * CHN * 8) out[i] = fmaxf(out[i], 0.f) + 1.f;
}

extern "C" void kernel_launch(void* const* d_in, const int* in_sizes, int n_in,
                              void* d_out, int out_size) {
    (void)in_sizes; (void)n_in; (void)out_size;
    const float* x = (const float*)d_in[0];   // x[16,256,256,3,8] fp32
    float* out = (float*)d_out;               // [16,3,8,8] fp32

    cudaFuncSetAttribute(sgb_main,
                         cudaFuncAttributeMaxDynamicSharedMemorySize,
                         SMEMBYTES);

    sgb_zero<<<12, 256>>>(out);
    dim3 grid(HW / CHUNK, HW / RT, 16);       // (8 chunks, 4 strips, 16 batch) = 512 CTAs
    sgb_main<<<grid, BLK, SMEMBYTES>>>(x, out);
    sgb_finalize<<<12, 256>>>(out);
}

// round 5
// speedup vs baseline: 1.9439x; 1.9439x over previous
#include <cuda_runtime.h>
#include <cuda_bf16.h>

// x[B=16, H=256, W=256, C=3, L=8] fp32 -> out[16,3,8,8]
// CHN = C*L = 24 floats = 6 float4 per (b,h,w) position.
#define HW    256
#define CHN   24
#define CHUNK 32          // output cols per CTA
#define RT    64          // output rows per CTA
#define BLK   192
#define HALO  7
#define NCMAX (CHUNK + HALO)       // 39 cols incl. halo
#define NFMAX (NCMAX * 6)          // 234 float4 items per plane row
#define P2W   204                  // p2 plane width (34 cols * 6)
#define ST2   210                  // p2 row stride (== 2 mod 8)
#define ST4   234                  // p4 row stride (== 2 mod 8)
#define RING  12                   // ring slots (12*ST == 0 mod 8)
#define SMEM_F4  (RING * (ST2 + ST4))   // 5328 float4
#define SMEMBYTES (SMEM_F4 * 16)        // 85248 B -> 2 CTAs/SM

__device__ __forceinline__ float4 fmax4(float4 a, float4 b) {
    return make_float4(fmaxf(a.x, b.x), fmaxf(a.y, b.y),
                       fmaxf(a.z, b.z), fmaxf(a.w, b.w));
}
__device__ __forceinline__ void fadd4(float4& a, float4 b) {
    a.x += b.x; a.y += b.y; a.z += b.z; a.w += b.w;
}

// Ring update for one item of one input row rr:
//   p2[rr-3] (delayed 2) and p4[rr-3] written when processing rr;
//   bottom edge flushes p2[253], p2[254].
__device__ __forceinline__ void ring_update(
    int rr, int r0, int rtEnd, int f, bool own, float4 xv,
    float4& xp, float4& m1, float4& m2,
    float4* __restrict__ P2, float4* __restrict__ P4, float4& acc0)
{
    if (own && rr < rtEnd) fadd4(acc0, xv);          // scale 1
    if (rr > r0) {
        float4 p2v = fmax4(xv, xp);                  // p2[rr-1]
        if (rr >= r0 + 3) {
            const int ws = (rr - 3) % RING;
            if (f < P2W) P2[ws * ST2 + f] = m2;      // p2[rr-3]
            P4[ws * ST4 + f] = fmax4(m2, p2v);       // p4[rr-3]
        }
        if (rr == HW - 1 && f < P2W) {               // bottom-edge p2 flush
            P2[((HW - 3) % RING) * ST2 + f] = m1;    // p2[253]
            P2[((HW - 2) % RING) * ST2 + f] = p2v;   // p2[254]
        }
        m2 = m1; m1 = p2v;
    }
    xp = xv;
}

// CTA = (batch, 64-row strip, 32-col chunk + 7 halo cols).
// Per 4-row batch: ring-update rows i+7..i+10 from prefetched regs, issue
// LDGs for rows i+11..i+14, ONE sync, then phase B computes horizontal
// window maxes for output rows i..i+3 via m2/m4 doubling (T=4 cols/thread).
__global__ __launch_bounds__(BLK, 2)
void sgb_main(const float* __restrict__ x, float* __restrict__ out) {
    extern __shared__ float4 sm[];
    float4* P2 = sm;                  // RING x ST2
    float4* P4 = sm + RING * ST2;     // RING x ST4

    const int t  = threadIdx.x;
    const int b  = blockIdx.z;
    const int r0 = blockIdx.y * RT;
    const int c0 = blockIdx.x * CHUNK;
    const int ncols = min(NCMAX, HW - c0);
    const int NF = ncols * 6;
    const int rtEnd = r0 + RT;
    const int rowmax = min(HW - 1, r0 + RT + 6);

    const bool has2 = (t + BLK < NF);
    float4 xp0 = {0,0,0,0}, m1_0 = {0,0,0,0}, m2_0 = {0,0,0,0};
    float4 xp1 = {0,0,0,0}, m1_1 = {0,0,0,0}, m2_1 = {0,0,0,0};
    float4 xbuf0[4], xbuf1[4];

    // phase-B mapping: t = ((g*6 + ch4)*4 + ri)
    const int ri  = t & 3;
    const int gch = t >> 2;
    const int ch4 = gch % 6;
    const int g   = gch / 6;
    const int baseitem = g * 24 + ch4;
    const int collim = HW - (c0 + g * 4);

    float4 acc[8];
#pragma unroll
    for (int s = 0; s < 8; ++s) acc[s] = make_float4(0.f, 0.f, 0.f, 0.f);

    const float4* X = (const float4*)x;

    // ---- prologue: rows r0..r0+6 direct; prefetch r0+7..r0+10 ----
    for (int rr = r0; rr <= r0 + 6; ++rr) {
        const float4* grow = X + ((size_t)(b * HW + rr) * HW + c0) * 6;
        ring_update(rr, r0, rtEnd, t, true, grow[t], xp0, m1_0, m2_0, P2, P4, acc[0]);
        if (has2)
            ring_update(rr, r0, rtEnd, t + BLK, false, grow[t + BLK], xp1, m1_1, m2_1, P2, P4, acc[0]);
    }
#pragma unroll
    for (int q = 0; q < 4; ++q) {
        const int rr = r0 + 7 + q;
        if (rr <= rowmax) {
            const float4* grow = X + ((size_t)(b * HW + rr) * HW + c0) * 6;
            xbuf0[q] = grow[t];
            if (has2) xbuf1[q] = grow[t + BLK];
        }
    }

    for (int i = r0; i < r0 + RT; i += 4) {
        // ---- ring updates for rows i+7..i+10 (from prefetched regs) ----
#pragma unroll
        for (int q = 0; q < 4; ++q) {
            const int rr = i + 7 + q;
            if (rr <= rowmax) {
                ring_update(rr, r0, rtEnd, t, true, xbuf0[q], xp0, m1_0, m2_0, P2, P4, acc[0]);
                if (has2)
                    ring_update(rr, r0, rtEnd, t + BLK, false, xbuf1[q], xp1, m1_1, m2_1, P2, P4, acc[0]);
            }
        }
        // ---- prefetch rows i+11..i+14 (latency hidden by phase B) ----
#pragma unroll
        for (int q = 0; q < 4; ++q) {
            const int rr = i + 11 + q;
            if (rr <= rowmax) {
                const float4* grow = X + ((size_t)(b * HW + rr) * HW + c0) * 6;
                xbuf0[q] = grow[t];
                if (has2) xbuf1[q] = grow[t + BLK];
            }
        }
        __syncthreads();

        // ---- phase B: output row o = i + ri ----
        const int o = i + ri;
        const int rlim = HW - o;
        const float4* p2o  = P2 + ((o    ) % RING) * ST2 + baseitem;
        const float4* p2o1 = P2 + ((o + 1) % RING) * ST2 + baseitem;
        const float4* p4o  = P4 + ((o    ) % RING) * ST4 + baseitem;
        const float4* p4o1 = P4 + ((o + 1) % RING) * ST4 + baseitem;
        const float4* p4o2 = P4 + ((o + 2) % RING) * ST4 + baseitem;
        const float4* p4o3 = P4 + ((o + 3) % RING) * ST4 + baseitem;
        const float4* p4o4 = P4 + ((o + 4) % RING) * ST4 + baseitem;

        // scales 2,3 from p2
        {
            float4 a[6];
#pragma unroll
            for (int k = 0; k < 6; ++k) a[k] = p2o[6 * k];
            if (rlim >= 2) {
                float4 s = make_float4(0.f, 0.f, 0.f, 0.f);
#pragma unroll
                for (int j = 0; j < 4; ++j)
                    if (j + 2 <= collim) fadd4(s, fmax4(a[j], a[j + 1]));
                fadd4(acc[1], s);
            }
            if (rlim >= 3) {
                float4 bb[6];
#pragma unroll
                for (int k = 0; k < 6; ++k) bb[k] = fmax4(a[k], p2o1[6 * k]);
                float4 s = make_float4(0.f, 0.f, 0.f, 0.f);
#pragma unroll
                for (int j = 0; j < 4; ++j)
                    if (j + 3 <= collim)
                        fadd4(s, fmax4(fmax4(bb[j], bb[j + 1]), bb[j + 2]));
                fadd4(acc[2], s);
            }
        }
        // scales 4..8 from p4 (a4 shared)
        {
            float4 a4[11];
#pragma unroll
            for (int k = 0; k < 11; ++k) a4[k] = p4o[6 * k];
            if (rlim >= 4) {
                float4 m2[6];
#pragma unroll
                for (int k = 0; k < 6; ++k) m2[k] = fmax4(a4[k], a4[k + 1]);
                float4 s = make_float4(0.f, 0.f, 0.f, 0.f);
#pragma unroll
                for (int j = 0; j < 4; ++j)
                    if (j + 4 <= collim) fadd4(s, fmax4(m2[j], m2[j + 2]));
                fadd4(acc[3], s);
            }
            if (rlim >= 5) {
                float4 bb[8];
#pragma unroll
                for (int k = 0; k < 8; ++k) bb[k] = fmax4(a4[k], p4o1[6 * k]);
                float4 m2[6];
#pragma unroll
                for (int k = 0; k < 6; ++k) m2[k] = fmax4(bb[k], bb[k + 1]);
                float4 s = make_float4(0.f, 0.f, 0.f, 0.f);
#pragma unroll
                for (int j = 0; j < 4; ++j)
                    if (j + 5 <= collim)
                        fadd4(s, fmax4(fmax4(m2[j], m2[j + 2]), bb[j + 4]));
                fadd4(acc[4], s);
            }
            if (rlim >= 6) {
                float4 bb[9];
#pragma unroll
                for (int k = 0; k < 9; ++k) bb[k] = fmax4(a4[k], p4o2[6 * k]);
                float4 m2[8];
#pragma unroll
                for (int k = 0; k < 8; ++k) m2[k] = fmax4(bb[k], bb[k + 1]);
                float4 s = make_float4(0.f, 0.f, 0.f, 0.f);
#pragma unroll
                for (int j = 0; j < 4; ++j)
                    if (j + 6 <= collim)
                        fadd4(s, fmax4(fmax4(m2[j], m2[j + 2]), m2[j + 4]));
                fadd4(acc[5], s);
            }
            if (rlim >= 7) {
                float4 bb[10];
#pragma unroll
                for (int k = 0; k < 10; ++k) bb[k] = fmax4(a4[k], p4o3[6 * k]);
                float4 m2[9];
#pragma unroll
                for (int k = 0; k < 9; ++k) m2[k] = fmax4(bb[k], bb[k + 1]);
                float4 m4[7];
#pragma unroll
                for (int j = 0; j < 7; ++j) m4[j] = fmax4(m2[j], m2[j + 2]);
                float4 s = make_float4(0.f, 0.f, 0.f, 0.f);
#pragma unroll
                for (int j = 0; j < 4; ++j)
                    if (j + 7 <= collim) fadd4(s, fmax4(m4[j], m4[j + 3]));
                fadd4(acc[6], s);
            }
            if (rlim >= 8) {
                float4 bb[11];
#pragma unroll
                for (int k = 0; k < 11; ++k) bb[k] = fmax4(a4[k], p4o4[6 * k]);
                float4 m2[10];
#pragma unroll
                for (int k = 0; k < 10; ++k) m2[k] = fmax4(bb[k], bb[k + 1]);
                float4 m4[8];
#pragma unroll
                for (int j = 0; j < 8; ++j) m4[j] = fmax4(m2[j], m2[j + 2]);
                float4 s = make_float4(0.f, 0.f, 0.f, 0.f);
#pragma unroll
                for (int j = 0; j < 4; ++j)
                    if (j + 8 <= collim) fadd4(s, fmax4(m4[j], m4[j + 4]));
                fadd4(acc[7], s);
            }
        }
        // no trailing sync: next iteration's ring writes (slots i+8..i+11)
        // are disjoint mod 12 from this phase B's reads (slots i..i+7).
    }

    // ---- block reduction: 32 owners per (ch4, scale); stride-33 pad ----
    __syncthreads();
    float4* red = sm;                 // 48*33 = 1584 float4, reuses rings
    red[((t % 6) * 8 + 0) * 33 + (t / 6)] = acc[0];     // scale 1 (load mapping)
#pragma unroll
    for (int si = 1; si < 8; ++si)
        red[(ch4 * 8 + si) * 33 + (g * 4 + ri)] = acc[si];
    __syncthreads();
    if (t < 48) {
        const int c4 = t >> 3, si = t & 7;
        float4 s = make_float4(0.f, 0.f, 0.f, 0.f);
        const float4* row = red + (c4 * 8 + si) * 33;
#pragma unroll 8
        for (int w = 0; w < 32; ++w) fadd4(s, row[w]);
        float* op = out + (size_t)b * (CHN * 8) + si;
        atomicAdd(op + (c4 * 4 + 0) * 8, s.x);
        atomicAdd(op + (c4 * 4 + 1) * 8, s.y);
        atomicAdd(op + (c4 * 4 + 2) * 8, s.z);
        atomicAdd(op + (c4 * 4 + 3) * 8, s.w);
    }
}

__global__ void sgb_zero(float* __restrict__ out) {
    int i = blockIdx.x * blockDim.x + threadIdx.x;
    if (i < 16 * CHN * 8) out[i] = 0.f;
}

__global__ void sgb_finalize(float* __restrict__ out) {
    int i = blockIdx.x * blockDim.x + threadIdx.x;
    if (i < 16 * CHN * 8) out[i] = fmaxf(out[i], 0.f) + 1.f;
}

extern "C" void kernel_launch(void* const* d_in, const int* in_sizes, int n_in,
                              void* d_out, int out_size) {
    (void)in_sizes; (void)n_in; (void)out_size;
    const float* x = (const float*)d_in[0];   // x[16,256,256,3,8] fp32
    float* out = (float*)d_out;               // [16,3,8,8] fp32

    cudaFuncSetAttribute(sgb_main,
                         cudaFuncAttributeMaxDynamicSharedMemorySize,
                         SMEMBYTES);

    sgb_zero<<<12, 256>>>(out);
    dim3 grid(HW / CHUNK, HW / RT, 16);       // (8 chunks, 4 strips, 16 batch) = 512 CTAs
    sgb_main<<<grid, BLK, SMEMBYTES>>>(x, out);
    sgb_finalize<<<12, 256>>>(out);
}